// round 2
// baseline (speedup 1.0000x reference)
#include <cuda_runtime.h>
#include <math.h>

#define N_NODES 30000
#define N_EDGES 480000
#define E_TOT   (N_EDGES + N_NODES)

// ---------------- scratch (static device globals; no allocation) ----------------
__device__ float g_bufA[N_NODES * 512];   // GEMM output h (per layer)
__device__ float g_bufB[N_NODES * 512];   // aggregated output (per layer)
__device__ float g_h3[N_NODES * 128];     // layer-3 h
__device__ float g_as[N_NODES * 4];
__device__ float g_ad[N_NODES * 4];
__device__ int   g_cnt[N_NODES];
__device__ int   g_off[N_NODES + 1];
__device__ int   g_cur[N_NODES];
__device__ int   g_csrc[E_TOT];
__device__ int   g_is64;

// ---------------- edge_index dtype probe ----------------
// The harness may deliver the int64 edge_index as int32. Detect on-device:
// if the int64 interpretation of the first 64 src/dst entries is in range,
// it's int64; otherwise treat the buffer as int32.
__global__ void k_detect(const void* __restrict__ ei) {
    if (threadIdx.x == 0) {
        const long long* p = (const long long*)ei;
        int ok = 1;
        for (int i = 0; i < 64; i++) {
            long long s = p[i];
            long long d = p[N_EDGES + i];
            if (s < 0 || s >= N_NODES || d < 0 || d >= N_NODES) { ok = 0; break; }
        }
        g_is64 = ok;
    }
}

__device__ __forceinline__ int edge_src(const void* ei, int i) {
    return g_is64 ? (int)((const long long*)ei)[i] : ((const int*)ei)[i];
}
__device__ __forceinline__ int edge_dst(const void* ei, int i) {
    return g_is64 ? (int)((const long long*)ei)[N_EDGES + i] : ((const int*)ei)[N_EDGES + i];
}

// ---------------- CSR build ----------------
__global__ void k_init_cnt() {
    int i = blockIdx.x * blockDim.x + threadIdx.x;
    if (i < N_NODES) g_cnt[i] = 1;   // self-loop
}

__global__ void k_count(const void* __restrict__ ei) {
    int i = blockIdx.x * blockDim.x + threadIdx.x;
    if (i < N_EDGES) {
        int d = edge_dst(ei, i);
        atomicAdd(&g_cnt[d], 1);
    }
}

__global__ void k_scan() {
    __shared__ int warpsums[32];
    __shared__ int carry;
    int tid = threadIdx.x;
    int lane = tid & 31, wid = tid >> 5;
    if (tid == 0) { carry = 0; g_off[0] = 0; }
    __syncthreads();
    for (int base = 0; base < N_NODES; base += 1024) {
        int i = base + tid;
        int v = (i < N_NODES) ? g_cnt[i] : 0;
        int x = v;
        #pragma unroll
        for (int d = 1; d < 32; d <<= 1) {
            int y = __shfl_up_sync(0xffffffffu, x, d);
            if (lane >= d) x += y;
        }
        if (lane == 31) warpsums[wid] = x;
        __syncthreads();
        if (wid == 0) {
            int s = warpsums[lane];
            #pragma unroll
            for (int d = 1; d < 32; d <<= 1) {
                int y = __shfl_up_sync(0xffffffffu, s, d);
                if (lane >= d) s += y;
            }
            warpsums[lane] = s;
        }
        __syncthreads();
        int incl = x + (wid > 0 ? warpsums[wid - 1] : 0) + carry;
        if (i < N_NODES) g_off[i + 1] = incl;
        __syncthreads();
        if (tid == 1023) carry = incl;
        __syncthreads();
    }
}

__global__ void k_copycur() {
    int i = blockIdx.x * blockDim.x + threadIdx.x;
    if (i < N_NODES) g_cur[i] = g_off[i];
}

__global__ void k_scatter(const void* __restrict__ ei) {
    int i = blockIdx.x * blockDim.x + threadIdx.x;
    if (i < N_EDGES) {
        int s = edge_src(ei, i);
        int d = edge_dst(ei, i);
        int pos = atomicAdd(&g_cur[d], 1);
        g_csrc[pos] = s;
    } else if (i < E_TOT) {
        int n = i - N_EDGES;
        int pos = atomicAdd(&g_cur[n], 1);
        g_csrc[pos] = n;
    }
}

// ---------------- SGEMM 128x128x8, fp32 ----------------
// A: MxK row-major, B: KxN row-major, C: MxN row-major. N%128==0, K%8==0.
__global__ __launch_bounds__(256) void k_sgemm(
    const float* __restrict__ A, const float* __restrict__ B, float* __restrict__ C,
    int M, int N, int K)
{
    __shared__ float As[8][132];
    __shared__ float Bs[8][132];

    int tid = threadIdx.x;
    int trow = (tid >> 4) * 8;
    int tcol = (tid & 15) * 8;

    int arow = tid >> 1;              // 0..127
    int acol = (tid & 1) * 4;         // 0 or 4
    int brow = tid >> 5;              // 0..7
    int bcol = (tid & 31) * 4;        // 0..124

    int gArow = blockIdx.y * 128 + arow;
    bool aval = gArow < M;
    const float* Aptr = A + (size_t)(aval ? gArow : 0) * K + acol;
    const float* Bptr = B + (size_t)brow * N + blockIdx.x * 128 + bcol;

    float acc[8][8];
    #pragma unroll
    for (int i = 0; i < 8; i++)
        #pragma unroll
        for (int j = 0; j < 8; j++) acc[i][j] = 0.f;

    for (int k0 = 0; k0 < K; k0 += 8) {
        float4 a4 = aval ? *(const float4*)Aptr : make_float4(0.f, 0.f, 0.f, 0.f);
        float4 b4 = *(const float4*)Bptr;
        As[acol + 0][arow] = a4.x;
        As[acol + 1][arow] = a4.y;
        As[acol + 2][arow] = a4.z;
        As[acol + 3][arow] = a4.w;
        *(float4*)&Bs[brow][bcol] = b4;
        __syncthreads();
        #pragma unroll
        for (int kk = 0; kk < 8; kk++) {
            float ar[8], br[8];
            *(float4*)(ar)     = *(const float4*)&As[kk][trow];
            *(float4*)(ar + 4) = *(const float4*)&As[kk][trow + 4];
            *(float4*)(br)     = *(const float4*)&Bs[kk][tcol];
            *(float4*)(br + 4) = *(const float4*)&Bs[kk][tcol + 4];
            #pragma unroll
            for (int i = 0; i < 8; i++)
                #pragma unroll
                for (int j = 0; j < 8; j++)
                    acc[i][j] = fmaf(ar[i], br[j], acc[i][j]);
        }
        __syncthreads();
        Aptr += 8;
        Bptr += (size_t)8 * N;
    }

    int crow0 = blockIdx.y * 128 + trow;
    int ccol0 = blockIdx.x * 128 + tcol;
    #pragma unroll
    for (int i = 0; i < 8; i++) {
        int r = crow0 + i;
        if (r < M) {
            float* cp = C + (size_t)r * N + ccol0;
            *(float4*)(cp)     = make_float4(acc[i][0], acc[i][1], acc[i][2], acc[i][3]);
            *(float4*)(cp + 4) = make_float4(acc[i][4], acc[i][5], acc[i][6], acc[i][7]);
        }
    }
}

// ---------------- attention projections ----------------
// H=4, C=128: block 128 threads = 4 warps, one node per block; warp w = head w.
__global__ void k_proj4(const float* __restrict__ h, const float* __restrict__ att_s,
                        const float* __restrict__ att_d)
{
    int n = blockIdx.x;
    int w = threadIdx.x >> 5, lane = threadIdx.x & 31;
    int c = w * 128 + lane * 4;
    float4 hv = *(const float4*)(h + (size_t)n * 512 + c);
    float4 sv = *(const float4*)(att_s + c);
    float4 dv = *(const float4*)(att_d + c);
    float ss = hv.x * sv.x + hv.y * sv.y + hv.z * sv.z + hv.w * sv.w;
    float dd = hv.x * dv.x + hv.y * dv.y + hv.z * dv.z + hv.w * dv.w;
    #pragma unroll
    for (int d = 16; d; d >>= 1) {
        ss += __shfl_xor_sync(0xffffffffu, ss, d);
        dd += __shfl_xor_sync(0xffffffffu, dd, d);
    }
    if (lane == 0) { g_as[n * 4 + w] = ss; g_ad[n * 4 + w] = dd; }
}

// H=1, C=128: warp per node, 8 nodes per 256-thread block.
__global__ void k_proj1(const float* __restrict__ h, const float* __restrict__ att_s,
                        const float* __restrict__ att_d)
{
    int node = blockIdx.x * 8 + (threadIdx.x >> 5);
    if (node >= N_NODES) return;
    int lane = threadIdx.x & 31;
    int c = lane * 4;
    float4 hv = *(const float4*)(h + (size_t)node * 128 + c);
    float4 sv = *(const float4*)(att_s + c);
    float4 dv = *(const float4*)(att_d + c);
    float ss = hv.x * sv.x + hv.y * sv.y + hv.z * sv.z + hv.w * sv.w;
    float dd = hv.x * dv.x + hv.y * dv.y + hv.z * dv.z + hv.w * dv.w;
    #pragma unroll
    for (int d = 16; d; d >>= 1) {
        ss += __shfl_xor_sync(0xffffffffu, ss, d);
        dd += __shfl_xor_sync(0xffffffffu, dd, d);
    }
    if (lane == 0) { g_as[node] = ss; g_ad[node] = dd; }
}

__device__ __forceinline__ float lrelu(float a) { return a > 0.f ? a : 0.2f * a; }

// ---------------- fused softmax + aggregation ----------------
// H=4, C=128: one dst node per 128-thread block; warp w = head w; lane owns 4 cols.
template<bool RELU>
__global__ void k_agg4(const float* __restrict__ h, const float* __restrict__ bias,
                       float* __restrict__ out)
{
    int n = blockIdx.x;
    int w = threadIdx.x >> 5, lane = threadIdx.x & 31;
    int beg = g_off[n], end = g_off[n + 1];
    float adst = g_ad[n * 4 + w];

    // phase 1: max of a_src over incoming edges (lrelu monotone => defer)
    float mx = -1e30f;
    for (int i = beg + lane; i < end; i += 32)
        mx = fmaxf(mx, g_as[g_csrc[i] * 4 + w]);
    #pragma unroll
    for (int d = 16; d; d >>= 1)
        mx = fmaxf(mx, __shfl_xor_sync(0xffffffffu, mx, d));
    float m = lrelu(mx + adst);

    // phase 2: accumulate exp(e-m)*h[src] and denom
    float4 acc = make_float4(0.f, 0.f, 0.f, 0.f);
    float denom = 0.f;
    int c0 = w * 128 + lane * 4;
    #pragma unroll 2
    for (int i = beg; i < end; i++) {
        int s = g_csrc[i];
        float a = lrelu(g_as[s * 4 + w] + adst);
        float ex = __expf(a - m);
        denom += ex;
        float4 hv = *(const float4*)(h + (size_t)s * 512 + c0);
        acc.x = fmaf(ex, hv.x, acc.x);
        acc.y = fmaf(ex, hv.y, acc.y);
        acc.z = fmaf(ex, hv.z, acc.z);
        acc.w = fmaf(ex, hv.w, acc.w);
    }
    float inv = 1.f / denom;
    float4 b = *(const float4*)(bias + c0);
    float4 o;
    o.x = acc.x * inv + b.x;
    o.y = acc.y * inv + b.y;
    o.z = acc.z * inv + b.z;
    o.w = acc.w * inv + b.w;
    if (RELU) {
        o.x = fmaxf(o.x, 0.f); o.y = fmaxf(o.y, 0.f);
        o.z = fmaxf(o.z, 0.f); o.w = fmaxf(o.w, 0.f);
    }
    *(float4*)(out + (size_t)n * 512 + c0) = o;
}

// H=1, C=128: warp per node, 8 nodes per 256-thread block. No relu; +bias.
__global__ void k_agg1(const float* __restrict__ h, const float* __restrict__ bias,
                       float* __restrict__ out)
{
    int node = blockIdx.x * 8 + (threadIdx.x >> 5);
    if (node >= N_NODES) return;
    int lane = threadIdx.x & 31;
    int beg = g_off[node], end = g_off[node + 1];
    float adst = g_ad[node];

    float mx = -1e30f;
    for (int i = beg + lane; i < end; i += 32)
        mx = fmaxf(mx, g_as[g_csrc[i]]);
    #pragma unroll
    for (int d = 16; d; d >>= 1)
        mx = fmaxf(mx, __shfl_xor_sync(0xffffffffu, mx, d));
    float m = lrelu(mx + adst);

    float4 acc = make_float4(0.f, 0.f, 0.f, 0.f);
    float denom = 0.f;
    int c0 = lane * 4;
    #pragma unroll 2
    for (int i = beg; i < end; i++) {
        int s = g_csrc[i];
        float a = lrelu(g_as[s] + adst);
        float ex = __expf(a - m);
        denom += ex;
        float4 hv = *(const float4*)(h + (size_t)s * 128 + c0);
        acc.x = fmaf(ex, hv.x, acc.x);
        acc.y = fmaf(ex, hv.y, acc.y);
        acc.z = fmaf(ex, hv.z, acc.z);
        acc.w = fmaf(ex, hv.w, acc.w);
    }
    float inv = 1.f / denom;
    float4 b = *(const float4*)(bias + c0);
    float4 o;
    o.x = acc.x * inv + b.x;
    o.y = acc.y * inv + b.y;
    o.z = acc.z * inv + b.z;
    o.w = acc.w * inv + b.w;
    *(float4*)(out + (size_t)node * 128 + c0) = o;
}

// ---------------- launch ----------------
extern "C" void kernel_launch(void* const* d_in, const int* in_sizes, int n_in,
                              void* d_out, int out_size)
{
    const float* x    = (const float*)d_in[0];
    const void*  ei   = d_in[1];
    const float* W1   = (const float*)d_in[2];
    const float* as1  = (const float*)d_in[3];
    const float* ad1  = (const float*)d_in[4];
    const float* b1   = (const float*)d_in[5];
    const float* W2   = (const float*)d_in[6];
    const float* as2  = (const float*)d_in[7];
    const float* ad2  = (const float*)d_in[8];
    const float* b2   = (const float*)d_in[9];
    const float* W3   = (const float*)d_in[10];
    const float* as3  = (const float*)d_in[11];
    const float* ad3  = (const float*)d_in[12];
    const float* b3   = (const float*)d_in[13];
    float*       out  = (float*)d_out;

    float *bufA, *bufB, *h3;
    cudaGetSymbolAddress((void**)&bufA, g_bufA);
    cudaGetSymbolAddress((void**)&bufB, g_bufB);
    cudaGetSymbolAddress((void**)&h3,   g_h3);

    // edge_index dtype probe + CSR build (dst-sorted incoming lists, self-loops included)
    k_detect<<<1, 32>>>(ei);
    k_init_cnt<<<(N_NODES + 255) / 256, 256>>>();
    k_count<<<(N_EDGES + 255) / 256, 256>>>(ei);
    k_scan<<<1, 1024>>>();
    k_copycur<<<(N_NODES + 255) / 256, 256>>>();
    k_scatter<<<(E_TOT + 255) / 256, 256>>>(ei);

    dim3 g1(512 / 128, (N_NODES + 127) / 128);
    dim3 g3(128 / 128, (N_NODES + 127) / 128);

    // layer 1
    k_sgemm<<<g1, 256>>>(x, W1, bufA, N_NODES, 512, 256);
    k_proj4<<<N_NODES, 128>>>(bufA, as1, ad1);
    k_agg4<true><<<N_NODES, 128>>>(bufA, b1, bufB);

    // layer 2
    k_sgemm<<<g1, 256>>>(bufB, W2, bufA, N_NODES, 512, 512);
    k_proj4<<<N_NODES, 128>>>(bufA, as2, ad2);
    k_agg4<true><<<N_NODES, 128>>>(bufA, b2, bufB);

    // layer 3
    k_sgemm<<<g3, 256>>>(bufB, W3, h3, N_NODES, 128, 512);
    k_proj1<<<(N_NODES + 7) / 8, 256>>>(h3, as3, ad3);
    k_agg1<<<(N_NODES + 7) / 8, 256>>>(h3, b3, out);
}